// round 15
// baseline (speedup 1.0000x reference)
#include <cuda_runtime.h>
#include <cuda_fp16.h>
#include <cstdint>

#define B_  16
#define T_  2048
#define R_  256
#define NS_ 4
#define BT_ (B_*T_)

// ----------------------------- device scratch ------------------------------
__device__ __half g_q16[(size_t)BT_*R_];
__device__ __half g_k16[(size_t)BT_*R_];
__device__ __half g_v16[(size_t)BT_*R_];
__device__ __half g_wq16[R_*R_], g_wk16[R_*R_];
__device__ __half g_wv16[NS_*R_*R_];
__device__ __half g_qp16[(size_t)BT_*R_];
__device__ __half g_kp16[(size_t)BT_*R_];
__device__ __half g_vt16[(size_t)NS_*B_*R_*T_];      // [n][b][r][t]
__device__ __half g_score[(size_t)B_*T_*T_];         // fp16 masked scores
__device__ __half g_a16[(size_t)B_*T_*T_];
__device__ float  g_projpart[2*NS_*B_*T_];           // [bx][n][b][t]
__device__ float  g_bloss[B_];
__device__ int    g_pdone;                            // pgemm completion counter

// ------------------------------- PTX helpers -------------------------------
static __device__ __forceinline__ uint32_t smem_u32(const void* p) {
    return (uint32_t)__cvta_generic_to_shared(p);
}
static __device__ __forceinline__ void cp16(uint32_t d, const void* s) {
    asm volatile("cp.async.cg.shared.global [%0], [%1], 16;" :: "r"(d), "l"(s));
}
static __device__ __forceinline__ uint32_t swz(uint32_t o) { return o ^ ((o >> 3) & 0x70); }

static __device__ __forceinline__ void ldsm4(uint32_t* r, uint32_t addr) {
    asm volatile("ldmatrix.sync.aligned.m8n8.x4.shared.b16 {%0,%1,%2,%3}, [%4];"
                 : "=r"(r[0]), "=r"(r[1]), "=r"(r[2]), "=r"(r[3]) : "r"(addr));
}
static __device__ __forceinline__ void hmma_f16(float* c, const uint32_t* a,
                                                uint32_t b0, uint32_t b1) {
    asm volatile(
        "mma.sync.aligned.m16n8k16.row.col.f32.f16.f16.f32 "
        "{%0,%1,%2,%3}, {%4,%5,%6,%7}, {%8,%9}, {%0,%1,%2,%3};"
        : "+f"(c[0]), "+f"(c[1]), "+f"(c[2]), "+f"(c[3])
        : "r"(a[0]), "r"(a[1]), "r"(a[2]), "r"(a[3]), "r"(b0), "r"(b1));
}
static __device__ __forceinline__ int ld_acquire(const int* p) {
    int v;
    asm volatile("ld.acquire.gpu.global.b32 %0, [%1];" : "=r"(v) : "l"(p) : "memory");
    return v;
}

// fp16 GEMM: 3 stages x 32KB (A,B tiles of 16KB, 128 rows x 128B SW128)
#define STAGE_B 32768
#define SMEM_G  98304

// --------------- fp16 GEMM core (3-stage, single barrier/chunk) ------------
static __device__ __forceinline__ void load_chunk(
    uint32_t st, const __half* __restrict__ A, long lda,
    const __half* __restrict__ B, long ldb, int k0, int tid)
{
    const int j = tid & 7, r0 = tid >> 3;
#pragma unroll
    for (int rr = 0; rr < 4; rr++) {
        const int row = r0 + rr * 32;
        const uint32_t d = swz((uint32_t)(row * 128 + j * 16));
        cp16(st + d,         A + (long)row * lda + k0 + j * 8);
        cp16(st + 16384 + d, B + (long)row * ldb + k0 + j * 8);
    }
    asm volatile("cp.async.commit_group;" ::: "memory");
}

static __device__ __forceinline__ void gemm_core(
    char* sm, const __half* A, long lda, const __half* B, long ldb,
    int NC, float acc[2][8][4])
{
    const int tid = threadIdx.x, lane = tid & 31, wid = tid >> 5;
    const int mOff = (wid & 3) * 32;
    const int nOff = (wid >> 2) * 64;
    const int aRow = lane & 15,                  aKb = (lane >> 4) << 4;
    const int bRow = (lane & 7) + ((lane >> 4) << 3), bKb = ((lane >> 3) & 1) << 4;
    const uint32_t sb = smem_u32(sm);

    load_chunk(sb, A, lda, B, ldb, 0, tid);
    if (NC > 1) load_chunk(sb + STAGE_B, A, lda, B, ldb, 64, tid);

    for (int c = 0; c < NC; c++) {
        if (c + 1 < NC) {
            asm volatile("cp.async.wait_group 1;" ::: "memory");
        } else {
            asm volatile("cp.async.wait_group 0;" ::: "memory");
        }
        __syncthreads();
        if (c + 2 < NC)
            load_chunk(sb + (uint32_t)((c + 2) % 3) * STAGE_B, A, lda, B, ldb, (c + 2) * 64, tid);

        const uint32_t st = sb + (uint32_t)(c % 3) * STAGE_B;
#pragma unroll
        for (int ks = 0; ks < 4; ks++) {
            const int kb = ks * 32;
            uint32_t aH[2][4], bH[4][4];
#pragma unroll
            for (int mt = 0; mt < 2; mt++) {
                const uint32_t off = swz((uint32_t)((mOff + mt * 16 + aRow) * 128 + kb + aKb));
                ldsm4(aH[mt], st + off);
            }
#pragma unroll
            for (int p = 0; p < 4; p++) {
                const uint32_t off = swz((uint32_t)((nOff + p * 16 + bRow) * 128 + kb + bKb));
                ldsm4(bH[p], st + 16384 + off);
            }
#pragma unroll
            for (int mt = 0; mt < 2; mt++)
#pragma unroll
                for (int nt = 0; nt < 8; nt++) {
                    const int p = nt >> 1, q = (nt & 1) << 1;
                    hmma_f16(acc[mt][nt], aH[mt], bH[p][q], bH[p][q + 1]);
                }
        }
    }
    __syncthreads();   // protect smem before caller's epilogue reuse
}

// ------------------------------ convert kernels ----------------------------
__global__ void __launch_bounds__(256) k_cvt3(const float* __restrict__ q,
                                              const float* __restrict__ k,
                                              const float* __restrict__ v)
{
    if (blockIdx.x == 0 && blockIdx.y == 0 && threadIdx.x == 0)
        g_pdone = 0;   // reset dependency counter (ordered by launch boundary)
    const float* x = (blockIdx.y == 0) ? q : (blockIdx.y == 1) ? k : v;
    __half* o = (blockIdx.y == 0) ? g_q16 : (blockIdx.y == 1) ? g_k16 : g_v16;
    const float4* __restrict__ x4 = (const float4*)x;
    __half2* __restrict__ o2 = (__half2*)o;
    const long n4 = ((long)BT_ * R_) >> 2;
    long i = (long)blockIdx.x * blockDim.x + threadIdx.x;
    const long stride = (long)gridDim.x * blockDim.x;
    for (; i < n4; i += stride) {
        const float4 t = x4[i];
        __half2 a; a.x = __float2half(t.x); a.y = __float2half(t.y);
        __half2 b; b.x = __float2half(t.z); b.y = __float2half(t.w);
        o2[2 * i] = a; o2[2 * i + 1] = b;
    }
}
__global__ void __launch_bounds__(256) k_cvtw(const float* __restrict__ wq,
                                              const float* __restrict__ wk,
                                              const float* __restrict__ wv)
{
    const float* x = (blockIdx.y == 0) ? wq : (blockIdx.y == 1) ? wk : wv;
    __half* o = (blockIdx.y == 0) ? g_wq16 : (blockIdx.y == 1) ? g_wk16 : g_wv16;
    const long n4 = (blockIdx.y == 2 ? (long)NS_ * R_ * R_ : (long)R_ * R_) >> 2;
    const float4* __restrict__ x4 = (const float4*)x;
    __half2* __restrict__ o2 = (__half2*)o;
    long i = (long)blockIdx.x * blockDim.x + threadIdx.x;
    const long stride = (long)gridDim.x * blockDim.x;
    for (; i < n4; i += stride) {
        const float4 t = x4[i];
        __half2 a; a.x = __float2half(t.x); a.y = __float2half(t.y);
        __half2 b; b.x = __float2half(t.z); b.y = __float2half(t.w);
        o2[2 * i] = a; o2[2 * i + 1] = b;
    }
}

// --- MID mega-kernel: qk-proj (0..1023) | vproj (1024..3071) | score (3072+)
// Score CTAs spin on g_pdone (released by the 1024 qk-proj CTAs). Deadlock-
// free: CTAs dispatch in bid order, so a resident score CTA implies all
// qk-proj CTAs are placed and retire independently of spinners.
#define PG_CTAS 1024
#define VP_CTAS 2048
#define SC_CTAS (136 * B_)
#define TPAD 136   // padded row stride (halfs) for the transpose buffer

__global__ void __launch_bounds__(256, 2) k_mid(const float* __restrict__ bq,
                                                const float* __restrict__ bk,
                                                const float* __restrict__ bv,
                                                const float* __restrict__ wp)
{
    extern __shared__ char sm[];
    const int tid = threadIdx.x, lane = tid & 31, wid = tid >> 5;
    const int g = lane >> 2, tg = lane & 3;
    const int mOff = (wid & 3) * 32, nOff = (wid >> 2) * 64;
    const int bid = blockIdx.x;

    if (bid < PG_CTAS) {
        // ----------------------- q/k projection path -----------------------
        const int which = bid >> 9;               // 0..1
        const int r = bid & 511;
        const int n0 = (r & 1) * 128;
        const int m0 = (r >> 1) * 128;

        const __half* X = (which == 0) ? g_q16 : g_k16;
        const __half* W = (which == 0) ? g_wq16 : g_wk16;
        const float* bias = (which == 0) ? bq : bk;

        float acc[2][8][4] = {};
        gemm_core(sm, X + (size_t)m0 * R_, R_, W + (size_t)n0 * R_, R_, R_ / 64, acc);

        __half* O = (which == 0) ? g_qp16 : g_kp16;
#pragma unroll
        for (int mt = 0; mt < 2; mt++)
#pragma unroll
            for (int nt = 0; nt < 8; nt++) {
                const int col = n0 + nOff + nt * 8 + 2 * tg;
                const float b0 = __ldg(bias + col), b1 = __ldg(bias + col + 1);
#pragma unroll
                for (int h = 0; h < 2; h++) {
                    const int row = m0 + mOff + mt * 16 + g + h * 8;
                    __half2 p;
                    p.x = __float2half(acc[mt][nt][h * 2 + 0] + b0);
                    p.y = __float2half(acc[mt][nt][h * 2 + 1] + b1);
                    *reinterpret_cast<__half2*>(O + (size_t)row * R_ + col) = p;
                }
            }
        // release: make writes visible, then count this CTA done
        __syncthreads();
        if (tid == 0) {
            __threadfence();
            atomicAdd(&g_pdone, 1);
        }
    } else if (bid < PG_CTAS + VP_CTAS) {
        // -------- v-projection path: GEMM + transpose + proj partials ------
        const int r2 = bid - PG_CTAS;              // 0..2047
        const int bx = r2 & 1;                     // n0 half
        const int by = (r2 >> 1) & 255;            // m tile
        const int z  = r2 >> 9;                    // n-state
        const int m0 = by * 128, n0 = bx * 128;
        const float* bz = bv + (size_t)z * R_;

        float acc[2][8][4] = {};
        gemm_core(sm, g_v16 + (size_t)m0 * R_, R_,
                      g_wv16 + (size_t)z * R_ * R_ + (size_t)n0 * R_, R_, R_ / 64, acc);

        const int b = m0 / T_, t0 = m0 % T_;

        __half* buf = (__half*)sm;
        float ps[2][2] = {};
#pragma unroll
        for (int mt = 0; mt < 2; mt++)
#pragma unroll
            for (int nt = 0; nt < 8; nt++) {
                const int colL = nOff + nt * 8 + 2 * tg;
                const float w0 = __ldg(wp + n0 + colL), w1 = __ldg(wp + n0 + colL + 1);
                const float b0 = __ldg(bz + n0 + colL), b1 = __ldg(bz + n0 + colL + 1);
#pragma unroll
                for (int h = 0; h < 2; h++) {
                    const int tL = mOff + mt * 16 + g + h * 8;
                    buf[(colL + 0) * TPAD + tL] = __float2half(acc[mt][nt][h * 2 + 0] + b0);
                    buf[(colL + 1) * TPAD + tL] = __float2half(acc[mt][nt][h * 2 + 1] + b1);
                    ps[mt][h] += acc[mt][nt][h * 2 + 0] * w0 + acc[mt][nt][h * 2 + 1] * w1;
                }
            }
        __syncthreads();

        const size_t base = ((size_t)z * B_ + b) * R_ * T_;
#pragma unroll
        for (int i = 0; i < 16; i++) {
            const int r = wid * 16 + i;
            const uint2 val = *reinterpret_cast<const uint2*>(buf + r * TPAD + lane * 4);
            *reinterpret_cast<uint2*>(g_vt16 + base + (size_t)(n0 + r) * T_ + t0 + lane * 4) = val;
        }
        __syncthreads();

        float* fb = (float*)sm;                    // 128 rows x 8 slots
        const int slot = (wid >> 2) * 4 + tg;
#pragma unroll
        for (int mt = 0; mt < 2; mt++)
#pragma unroll
            for (int h = 0; h < 2; h++) {
                const int rowL = mOff + mt * 16 + g + h * 8;
                fb[rowL * 8 + slot] = ps[mt][h];
            }
        __syncthreads();
        if (tid < 128) {
            float s = 0.f;
#pragma unroll
            for (int q = 0; q < 8; q++) s += fb[tid * 8 + q];
            const size_t idxp = (((size_t)bx * NS_ + z) * B_ + b) * T_ + t0 + tid;
            g_projpart[idxp] = s;
        }
    } else {
        // ---------------- score path: lower-triangular tile ----------------
        // acquire: wait for all qk-proj CTAs
        if (tid == 0) {
            while (ld_acquire(&g_pdone) < PG_CTAS) { }
        }
        __syncthreads();

        const int rr = bid - PG_CTAS - VP_CTAS;
        const int b = rr / 136;
        const int idx = rr % 136;
        int bi = (int)((sqrtf(8.0f * idx + 1.0f) - 1.0f) * 0.5f);
        while ((bi + 1) * (bi + 2) / 2 <= idx) ++bi;
        while (bi * (bi + 1) / 2 > idx) --bi;
        const int bj = idx - bi * (bi + 1) / 2;
        const int m0 = bi * 128, n0 = bj * 128;

        float acc[2][8][4] = {};
        gemm_core(sm, g_qp16 + ((size_t)b * T_ + m0) * R_, R_,
                      g_kp16 + ((size_t)b * T_ + n0) * R_, R_, R_ / 64, acc);

        __half* C = g_score + (size_t)b * T_ * T_;
#pragma unroll
        for (int mt = 0; mt < 2; mt++)
#pragma unroll
            for (int nt = 0; nt < 8; nt++) {
                const int gc = n0 + nOff + nt * 8 + 2 * tg;
#pragma unroll
                for (int h = 0; h < 2; h++) {
                    const int gr = m0 + mOff + mt * 16 + g + h * 8;
                    float v0 = acc[mt][nt][h * 2 + 0] * 0.0625f;
                    float v1 = acc[mt][nt][h * 2 + 1] * 0.0625f;
                    if (gc + 0 > gr || v0 == 0.0f) v0 = -1e4f;   // quirk on fp32 value
                    if (gc + 1 > gr || v1 == 0.0f) v1 = -1e4f;
                    __half2 p;
                    p.x = __float2half(v0);
                    p.y = __float2half(v1);
                    *reinterpret_cast<__half2*>(C + (size_t)gr * T_ + gc) = p;
                }
            }
    }
}

// ------- PHASE 3: softmax (fp16 in/out, half2) + fused covariance ----------
// grid.x = B_*T_ softmax rows + B_ cov blocks
__global__ void __launch_bounds__(256) k_phase3()
{
    __shared__ float red[256];
    const int tid = threadIdx.x;

    if (blockIdx.x < (unsigned)(B_ * T_)) {
        const int gr = blockIdx.x;             // b*T_ + r
        const int r = gr & (T_ - 1);
        const int Ceil2 = ((r & ~127) + 128) >> 1;
        const __half2* p2 = (const __half2*)(g_score + (size_t)gr * T_);
        __half2* pa2 = (__half2*)(g_a16 + (size_t)gr * T_);

        float v[8];
        float mx = -3.4e38f;
#pragma unroll
        for (int i = 0; i < 4; i++) {
            const int c2 = tid + i * 256;
            if (c2 < Ceil2) {
                const __half2 h = p2[c2];
                v[2*i]   = __half2float(h.x);
                v[2*i+1] = __half2float(h.y);
            } else {
                v[2*i] = v[2*i+1] = -3.4e38f;
            }
            mx = fmaxf(mx, fmaxf(v[2*i], v[2*i+1]));
        }
        red[tid] = mx; __syncthreads();
        for (int s = 128; s > 0; s >>= 1) {
            if (tid < s) red[tid] = fmaxf(red[tid], red[tid + s]);
            __syncthreads();
        }
        mx = red[0]; __syncthreads();

        float sum = 0.f;
#pragma unroll
        for (int i = 0; i < 4; i++) {
            const int c2 = tid + i * 256;
            if (c2 < Ceil2) {
                v[2*i]   = __expf(v[2*i]   - mx);
                v[2*i+1] = __expf(v[2*i+1] - mx);
                sum += v[2*i] + v[2*i+1];
            } else {
                v[2*i] = v[2*i+1] = 0.f;
            }
        }
        red[tid] = sum; __syncthreads();
        for (int s = 128; s > 0; s >>= 1) {
            if (tid < s) red[tid] += red[tid + s];
            __syncthreads();
        }
        const float inv = 1.0f / red[0];
#pragma unroll
        for (int i = 0; i < 4; i++) {
            const int c2 = tid + i * 256;
            if (c2 < Ceil2) {
                __half2 o;
                o.x = __float2half(v[2*i]   * inv);
                o.y = __float2half(v[2*i+1] * inv);
                pa2[c2] = o;
            }
        }
    } else {
        // ------------------------- covariance path -------------------------
        __shared__ float X[NS_][T_];
        const int b = blockIdx.x - B_ * T_;
        for (int i = tid; i < NS_ * T_; i += 256) {
            const int n = i / T_, t = i % T_;
            const size_t i0 = (((size_t)0 * NS_ + n) * B_ + b) * T_ + t;
            const size_t i1 = (((size_t)1 * NS_ + n) * B_ + b) * T_ + t;
            X[n][t] = g_projpart[i0] + g_projpart[i1];
        }
        __syncthreads();

        float mean[NS_];
#pragma unroll
        for (int n = 0; n < NS_; n++) {
            float s = 0.f;
            for (int t = tid; t < T_; t += 256) s += X[n][t];
            red[tid] = s; __syncthreads();
            for (int st = 128; st > 0; st >>= 1) {
                if (tid < st) red[tid] += red[tid + st];
                __syncthreads();
            }
            mean[n] = red[0] / (float)T_;
            __syncthreads();
        }

        float total = 0.f;
#pragma unroll
        for (int i = 0; i < NS_; i++)
#pragma unroll
            for (int j = 0; j <= i; j++) {
                float s = 0.f;
                for (int t = tid; t < T_; t += 256)
                    s += (X[i][t] - mean[i]) * (X[j][t] - mean[j]);
                red[tid] = s; __syncthreads();
                for (int st = 128; st > 0; st >>= 1) {
                    if (tid < st) red[tid] += red[tid + st];
                    __syncthreads();
                }
                if (tid == 0) {
                    const float c = red[0] / (float)(T_ - 1);
                    total += (i == j ? 1.0f : 2.0f) * fabsf(c);
                }
                __syncthreads();
            }
        if (tid == 0) g_bloss[b] = 0.5f * total;
    }
}

// --------------------------------- AV GEMM ---------------------------------
// grid (2, 4, 256): x=n0, y=n (A-tile sharers launch-adjacent), z=b*16+i,
// myi = 15-i (heavy tiles first).
__global__ void __launch_bounds__(256, 2) k_avgemm(float* __restrict__ out)
{
    extern __shared__ char sm[];
    const int tid = threadIdx.x, lane = tid & 31, wid = tid >> 5;
    const int n = blockIdx.y;
    const int b = blockIdx.z >> 4;
    const int myi = 15 - (int)(blockIdx.z & 15);
    const int m0 = myi * 128, n0 = blockIdx.x * 128;
    const int NC = myi * 2 + 2;            // causal: attn==0 beyond m0+128

    float acc[2][8][4] = {};
    gemm_core(sm, g_a16 + ((size_t)b * T_ + m0) * T_, T_,
                  g_vt16 + (((size_t)n * B_ + b) * R_ + n0) * T_, T_, NC, acc);

    float* C = out + ((size_t)b * NS_ + n) * T_ * R_;
    const int g = lane >> 2, tg = lane & 3;
    const int mOff = (wid & 3) * 32, nOff = (wid >> 2) * 64;
#pragma unroll
    for (int mt = 0; mt < 2; mt++)
#pragma unroll
        for (int nt = 0; nt < 8; nt++) {
            const int gc = n0 + nOff + nt * 8 + 2 * tg;
#pragma unroll
            for (int h = 0; h < 2; h++) {
                const int gr = m0 + mOff + mt * 16 + g + h * 8;
                *reinterpret_cast<float2*>(C + (size_t)gr * R_ + gc) =
                    make_float2(acc[mt][nt][h * 2 + 0], acc[mt][nt][h * 2 + 1]);
            }
        }
}

__global__ void k_final(float* __restrict__ out, long idx)
{
    float s = 0.f;
#pragma unroll
    for (int b = 0; b < B_; b++) s += g_bloss[b];
    out[idx] = s / (float)B_;
}

// ---------------------------------------------------------------------------
extern "C" void kernel_launch(void* const* d_in, const int* in_sizes, int n_in,
                              void* d_out, int out_size)
{
    (void)in_sizes; (void)n_in;
    const float* q  = (const float*)d_in[0];
    const float* k  = (const float*)d_in[1];
    const float* v  = (const float*)d_in[2];
    const float* wq = (const float*)d_in[3];
    const float* bq = (const float*)d_in[4];
    const float* wk = (const float*)d_in[5];
    const float* bk = (const float*)d_in[6];
    const float* wv = (const float*)d_in[7];
    const float* bv = (const float*)d_in[8];
    const float* wp = (const float*)d_in[9];
    float* out = (float*)d_out;

    static bool attr_set = false;
    if (!attr_set) {
        cudaFuncSetAttribute(k_mid,    cudaFuncAttributeMaxDynamicSharedMemorySize, SMEM_G);
        cudaFuncSetAttribute(k_avgemm, cudaFuncAttributeMaxDynamicSharedMemorySize, SMEM_G);
        attr_set = true;
    }

    const dim3 blk(256);
    k_cvt3<<<dim3(1024, 3), blk>>>(q, k, v);
    k_cvtw<<<dim3(64, 3),  blk>>>(wq, wk, wv);

    k_mid<<<PG_CTAS + VP_CTAS + SC_CTAS, blk, SMEM_G>>>(bq, bk, bv, wp);

    k_phase3<<<B_ * T_ + B_, blk>>>();

    k_avgemm<<<dim3(2, NS_, 256), blk, SMEM_G>>>(out);

    k_final<<<1, 1>>>(out, (long)out_size - 1);
}

// round 16
// speedup vs baseline: 1.1039x; 1.1039x over previous
#include <cuda_runtime.h>
#include <cuda_fp16.h>
#include <cstdint>

#define B_  16
#define T_  2048
#define R_  256
#define NS_ 4
#define BT_ (B_*T_)

// ----------------------------- device scratch ------------------------------
__device__ __half g_q16[(size_t)BT_*R_];
__device__ __half g_k16[(size_t)BT_*R_];
__device__ __half g_v16[(size_t)BT_*R_];
__device__ __half g_wq16[R_*R_], g_wk16[R_*R_];
__device__ __half g_wv16[NS_*R_*R_];
__device__ __half g_qp16[(size_t)BT_*R_];
__device__ __half g_kp16[(size_t)BT_*R_];
__device__ __half g_vt16[(size_t)NS_*B_*R_*T_];      // [n][b][r][t]
__device__ __half g_score[(size_t)B_*T_*T_];         // fp16 masked scores
__device__ __half g_a16[(size_t)B_*T_*T_];
__device__ float  g_projpart[2*NS_*B_*T_];           // [bx][n][b][t]
__device__ float  g_bloss[B_];
__device__ int    g_pdone;                            // pgemm completion counter

// ------------------------------- PTX helpers -------------------------------
static __device__ __forceinline__ uint32_t smem_u32(const void* p) {
    return (uint32_t)__cvta_generic_to_shared(p);
}
static __device__ __forceinline__ void cp16(uint32_t d, const void* s) {
    asm volatile("cp.async.cg.shared.global [%0], [%1], 16;" :: "r"(d), "l"(s));
}
static __device__ __forceinline__ uint32_t swz(uint32_t o) { return o ^ ((o >> 3) & 0x70); }

static __device__ __forceinline__ void ldsm4(uint32_t* r, uint32_t addr) {
    asm volatile("ldmatrix.sync.aligned.m8n8.x4.shared.b16 {%0,%1,%2,%3}, [%4];"
                 : "=r"(r[0]), "=r"(r[1]), "=r"(r[2]), "=r"(r[3]) : "r"(addr));
}
static __device__ __forceinline__ void hmma_f16(float* c, const uint32_t* a,
                                                uint32_t b0, uint32_t b1) {
    asm volatile(
        "mma.sync.aligned.m16n8k16.row.col.f32.f16.f16.f32 "
        "{%0,%1,%2,%3}, {%4,%5,%6,%7}, {%8,%9}, {%0,%1,%2,%3};"
        : "+f"(c[0]), "+f"(c[1]), "+f"(c[2]), "+f"(c[3])
        : "r"(a[0]), "r"(a[1]), "r"(a[2]), "r"(a[3]), "r"(b0), "r"(b1));
}
static __device__ __forceinline__ int ld_acquire(const int* p) {
    int v;
    asm volatile("ld.acquire.gpu.global.b32 %0, [%1];" : "=r"(v) : "l"(p) : "memory");
    return v;
}

// fp16 GEMM: 3 stages x 32KB (A,B tiles of 16KB, 128 rows x 128B SW128)
#define STAGE_B 32768
#define SMEM_G  98304

// --------------- fp16 GEMM core (3-stage, single barrier/chunk) ------------
static __device__ __forceinline__ void load_chunk(
    uint32_t st, const __half* __restrict__ A, long lda,
    const __half* __restrict__ B, long ldb, int k0, int tid)
{
    const int j = tid & 7, r0 = tid >> 3;
#pragma unroll
    for (int rr = 0; rr < 4; rr++) {
        const int row = r0 + rr * 32;
        const uint32_t d = swz((uint32_t)(row * 128 + j * 16));
        cp16(st + d,         A + (long)row * lda + k0 + j * 8);
        cp16(st + 16384 + d, B + (long)row * ldb + k0 + j * 8);
    }
    asm volatile("cp.async.commit_group;" ::: "memory");
}

static __device__ __forceinline__ void gemm_core(
    char* sm, const __half* A, long lda, const __half* B, long ldb,
    int NC, float acc[2][8][4])
{
    const int tid = threadIdx.x, lane = tid & 31, wid = tid >> 5;
    const int mOff = (wid & 3) * 32;
    const int nOff = (wid >> 2) * 64;
    const int aRow = lane & 15,                  aKb = (lane >> 4) << 4;
    const int bRow = (lane & 7) + ((lane >> 4) << 3), bKb = ((lane >> 3) & 1) << 4;
    const uint32_t sb = smem_u32(sm);

    load_chunk(sb, A, lda, B, ldb, 0, tid);
    if (NC > 1) load_chunk(sb + STAGE_B, A, lda, B, ldb, 64, tid);

    for (int c = 0; c < NC; c++) {
        if (c + 1 < NC) {
            asm volatile("cp.async.wait_group 1;" ::: "memory");
        } else {
            asm volatile("cp.async.wait_group 0;" ::: "memory");
        }
        __syncthreads();
        if (c + 2 < NC)
            load_chunk(sb + (uint32_t)((c + 2) % 3) * STAGE_B, A, lda, B, ldb, (c + 2) * 64, tid);

        const uint32_t st = sb + (uint32_t)(c % 3) * STAGE_B;
#pragma unroll
        for (int ks = 0; ks < 4; ks++) {
            const int kb = ks * 32;
            uint32_t aH[2][4], bH[4][4];
#pragma unroll
            for (int mt = 0; mt < 2; mt++) {
                const uint32_t off = swz((uint32_t)((mOff + mt * 16 + aRow) * 128 + kb + aKb));
                ldsm4(aH[mt], st + off);
            }
#pragma unroll
            for (int p = 0; p < 4; p++) {
                const uint32_t off = swz((uint32_t)((nOff + p * 16 + bRow) * 128 + kb + bKb));
                ldsm4(bH[p], st + 16384 + off);
            }
#pragma unroll
            for (int mt = 0; mt < 2; mt++)
#pragma unroll
                for (int nt = 0; nt < 8; nt++) {
                    const int p = nt >> 1, q = (nt & 1) << 1;
                    hmma_f16(acc[mt][nt], aH[mt], bH[p][q], bH[p][q + 1]);
                }
        }
    }
    __syncthreads();   // protect smem before caller's epilogue reuse
}

// ------------------------------ convert kernels ----------------------------
__global__ void __launch_bounds__(256) k_cvt3(const float* __restrict__ q,
                                              const float* __restrict__ k,
                                              const float* __restrict__ v)
{
    if (blockIdx.x == 0 && blockIdx.y == 0 && threadIdx.x == 0)
        g_pdone = 0;   // reset dependency counter (ordered by launch boundary)
    const float* x = (blockIdx.y == 0) ? q : (blockIdx.y == 1) ? k : v;
    __half* o = (blockIdx.y == 0) ? g_q16 : (blockIdx.y == 1) ? g_k16 : g_v16;
    const float4* __restrict__ x4 = (const float4*)x;
    __half2* __restrict__ o2 = (__half2*)o;
    const long n4 = ((long)BT_ * R_) >> 2;
    long i = (long)blockIdx.x * blockDim.x + threadIdx.x;
    const long stride = (long)gridDim.x * blockDim.x;
    for (; i < n4; i += stride) {
        const float4 t = x4[i];
        __half2 a; a.x = __float2half(t.x); a.y = __float2half(t.y);
        __half2 b; b.x = __float2half(t.z); b.y = __float2half(t.w);
        o2[2 * i] = a; o2[2 * i + 1] = b;
    }
}
__global__ void __launch_bounds__(256) k_cvtw(const float* __restrict__ wq,
                                              const float* __restrict__ wk,
                                              const float* __restrict__ wv)
{
    const float* x = (blockIdx.y == 0) ? wq : (blockIdx.y == 1) ? wk : wv;
    __half* o = (blockIdx.y == 0) ? g_wq16 : (blockIdx.y == 1) ? g_wk16 : g_wv16;
    const long n4 = (blockIdx.y == 2 ? (long)NS_ * R_ * R_ : (long)R_ * R_) >> 2;
    const float4* __restrict__ x4 = (const float4*)x;
    __half2* __restrict__ o2 = (__half2*)o;
    long i = (long)blockIdx.x * blockDim.x + threadIdx.x;
    const long stride = (long)gridDim.x * blockDim.x;
    for (; i < n4; i += stride) {
        const float4 t = x4[i];
        __half2 a; a.x = __float2half(t.x); a.y = __float2half(t.y);
        __half2 b; b.x = __float2half(t.z); b.y = __float2half(t.w);
        o2[2 * i] = a; o2[2 * i + 1] = b;
    }
}

// --- MID mega-kernel: qk-proj (0..1023) | vproj (1024..3071) | score (3072+)
#define PG_CTAS 1024
#define VP_CTAS 2048
#define SC_CTAS (136 * B_)
#define TPAD 136   // padded row stride (halfs) for the transpose buffer

__global__ void __launch_bounds__(256, 2) k_mid(const float* __restrict__ bq,
                                                const float* __restrict__ bk,
                                                const float* __restrict__ bv,
                                                const float* __restrict__ wp)
{
    extern __shared__ char sm[];
    const int tid = threadIdx.x, lane = tid & 31, wid = tid >> 5;
    const int g = lane >> 2, tg = lane & 3;
    const int mOff = (wid & 3) * 32, nOff = (wid >> 2) * 64;
    const int bid = blockIdx.x;

    if (bid < PG_CTAS) {
        // ----------------------- q/k projection path -----------------------
        const int which = bid >> 9;               // 0..1
        const int r = bid & 511;
        const int n0 = (r & 1) * 128;
        const int m0 = (r >> 1) * 128;

        const __half* X = (which == 0) ? g_q16 : g_k16;
        const __half* W = (which == 0) ? g_wq16 : g_wk16;
        const float* bias = (which == 0) ? bq : bk;

        float acc[2][8][4] = {};
        gemm_core(sm, X + (size_t)m0 * R_, R_, W + (size_t)n0 * R_, R_, R_ / 64, acc);

        __half* O = (which == 0) ? g_qp16 : g_kp16;
#pragma unroll
        for (int mt = 0; mt < 2; mt++)
#pragma unroll
            for (int nt = 0; nt < 8; nt++) {
                const int col = n0 + nOff + nt * 8 + 2 * tg;
                const float b0 = __ldg(bias + col), b1 = __ldg(bias + col + 1);
#pragma unroll
                for (int h = 0; h < 2; h++) {
                    const int row = m0 + mOff + mt * 16 + g + h * 8;
                    __half2 p;
                    p.x = __float2half(acc[mt][nt][h * 2 + 0] + b0);
                    p.y = __float2half(acc[mt][nt][h * 2 + 1] + b1);
                    *reinterpret_cast<__half2*>(O + (size_t)row * R_ + col) = p;
                }
            }
        __syncthreads();
        if (tid == 0) {
            __threadfence();
            atomicAdd(&g_pdone, 1);
        }
    } else if (bid < PG_CTAS + VP_CTAS) {
        // -------- v-projection path: GEMM + transpose + proj partials ------
        const int r2 = bid - PG_CTAS;              // 0..2047
        const int bx = r2 & 1;                     // n0 half
        const int by = (r2 >> 1) & 255;            // m tile
        const int z  = r2 >> 9;                    // n-state
        const int m0 = by * 128, n0 = bx * 128;
        const float* bz = bv + (size_t)z * R_;

        float acc[2][8][4] = {};
        gemm_core(sm, g_v16 + (size_t)m0 * R_, R_,
                      g_wv16 + (size_t)z * R_ * R_ + (size_t)n0 * R_, R_, R_ / 64, acc);

        const int b = m0 / T_, t0 = m0 % T_;

        __half* buf = (__half*)sm;
        float ps[2][2] = {};
#pragma unroll
        for (int mt = 0; mt < 2; mt++)
#pragma unroll
            for (int nt = 0; nt < 8; nt++) {
                const int colL = nOff + nt * 8 + 2 * tg;
                const float w0 = __ldg(wp + n0 + colL), w1 = __ldg(wp + n0 + colL + 1);
                const float b0 = __ldg(bz + n0 + colL), b1 = __ldg(bz + n0 + colL + 1);
#pragma unroll
                for (int h = 0; h < 2; h++) {
                    const int tL = mOff + mt * 16 + g + h * 8;
                    buf[(colL + 0) * TPAD + tL] = __float2half(acc[mt][nt][h * 2 + 0] + b0);
                    buf[(colL + 1) * TPAD + tL] = __float2half(acc[mt][nt][h * 2 + 1] + b1);
                    ps[mt][h] += acc[mt][nt][h * 2 + 0] * w0 + acc[mt][nt][h * 2 + 1] * w1;
                }
            }
        __syncthreads();

        const size_t base = ((size_t)z * B_ + b) * R_ * T_;
#pragma unroll
        for (int i = 0; i < 16; i++) {
            const int r = wid * 16 + i;
            const uint2 val = *reinterpret_cast<const uint2*>(buf + r * TPAD + lane * 4);
            *reinterpret_cast<uint2*>(g_vt16 + base + (size_t)(n0 + r) * T_ + t0 + lane * 4) = val;
        }
        __syncthreads();

        float* fb = (float*)sm;                    // 128 rows x 8 slots
        const int slot = (wid >> 2) * 4 + tg;
#pragma unroll
        for (int mt = 0; mt < 2; mt++)
#pragma unroll
            for (int h = 0; h < 2; h++) {
                const int rowL = mOff + mt * 16 + g + h * 8;
                fb[rowL * 8 + slot] = ps[mt][h];
            }
        __syncthreads();
        if (tid < 128) {
            float s = 0.f;
#pragma unroll
            for (int q = 0; q < 8; q++) s += fb[tid * 8 + q];
            const size_t idxp = (((size_t)bx * NS_ + z) * B_ + b) * T_ + t0 + tid;
            g_projpart[idxp] = s;
        }
    } else {
        // ---------------- score path: lower-triangular tile ----------------
        if (tid == 0) {
            while (ld_acquire(&g_pdone) < PG_CTAS) { }
        }
        __syncthreads();

        const int rr = bid - PG_CTAS - VP_CTAS;
        const int b = rr / 136;
        const int idx = rr % 136;
        int bi = (int)((sqrtf(8.0f * idx + 1.0f) - 1.0f) * 0.5f);
        while ((bi + 1) * (bi + 2) / 2 <= idx) ++bi;
        while (bi * (bi + 1) / 2 > idx) --bi;
        const int bj = idx - bi * (bi + 1) / 2;
        const int m0 = bi * 128, n0 = bj * 128;

        float acc[2][8][4] = {};
        gemm_core(sm, g_qp16 + ((size_t)b * T_ + m0) * R_, R_,
                      g_kp16 + ((size_t)b * T_ + n0) * R_, R_, R_ / 64, acc);

        __half* C = g_score + (size_t)b * T_ * T_;
#pragma unroll
        for (int mt = 0; mt < 2; mt++)
#pragma unroll
            for (int nt = 0; nt < 8; nt++) {
                const int gc = n0 + nOff + nt * 8 + 2 * tg;
#pragma unroll
                for (int h = 0; h < 2; h++) {
                    const int gr = m0 + mOff + mt * 16 + g + h * 8;
                    float v0 = acc[mt][nt][h * 2 + 0] * 0.0625f;
                    float v1 = acc[mt][nt][h * 2 + 1] * 0.0625f;
                    if (gc + 0 > gr || v0 == 0.0f) v0 = -1e4f;   // quirk on fp32 value
                    if (gc + 1 > gr || v1 == 0.0f) v1 = -1e4f;
                    __half2 p;
                    p.x = __float2half(v0);
                    p.y = __float2half(v1);
                    *reinterpret_cast<__half2*>(C + (size_t)gr * T_ + gc) = p;
                }
            }
    }
}

// ------- PHASE 3: warp-per-row softmax (barrier-free) + fused covariance ---
// grid.x = B_*T_/8 softmax blocks (8 warps x 1 row) + B_ cov blocks
#define SM_BLOCKS (B_ * T_ / 8)
__global__ void __launch_bounds__(256) k_phase3()
{
    const int tid = threadIdx.x;

    if (blockIdx.x < (unsigned)SM_BLOCKS) {
        const int lane = tid & 31, w = tid >> 5;
        // heavy rows first: reverse block order
        const int gr = (SM_BLOCKS - 1 - (int)blockIdx.x) * 8 + w;   // b*T_ + r
        const int r = gr & (T_ - 1);
        const int Ceil2 = ((r & ~127) + 128) >> 1;   // half2 extent (mult of 64)
        const __half2* p2 = (const __half2*)(g_score + (size_t)gr * T_);
        __half2* pa2 = (__half2*)(g_a16 + (size_t)gr * T_);

        // pass 1: max
        float mx = -3.4e38f;
        for (int c2 = lane; c2 < Ceil2; c2 += 32) {
            const __half2 h = p2[c2];
            mx = fmaxf(mx, fmaxf(__half2float(h.x), __half2float(h.y)));
        }
#pragma unroll
        for (int o = 16; o > 0; o >>= 1)
            mx = fmaxf(mx, __shfl_xor_sync(0xffffffffu, mx, o));

        // pass 2: sum of exp (row is L1-resident after pass 1)
        float sum = 0.f;
        for (int c2 = lane; c2 < Ceil2; c2 += 32) {
            const __half2 h = p2[c2];
            sum += __expf(__half2float(h.x) - mx) + __expf(__half2float(h.y) - mx);
        }
#pragma unroll
        for (int o = 16; o > 0; o >>= 1)
            sum += __shfl_xor_sync(0xffffffffu, sum, o);
        const float inv = 1.0f / sum;

        // pass 3: write normalized attn
        for (int c2 = lane; c2 < Ceil2; c2 += 32) {
            const __half2 h = p2[c2];
            __half2 o;
            o.x = __float2half(__expf(__half2float(h.x) - mx) * inv);
            o.y = __float2half(__expf(__half2float(h.y) - mx) * inv);
            pa2[c2] = o;
        }
    } else {
        // ------------------------- covariance path -------------------------
        __shared__ float X[NS_][T_];
        __shared__ float red[256];
        const int b = blockIdx.x - SM_BLOCKS;
        for (int i = tid; i < NS_ * T_; i += 256) {
            const int n = i / T_, t = i % T_;
            const size_t i0 = (((size_t)0 * NS_ + n) * B_ + b) * T_ + t;
            const size_t i1 = (((size_t)1 * NS_ + n) * B_ + b) * T_ + t;
            X[n][t] = g_projpart[i0] + g_projpart[i1];
        }
        __syncthreads();

        float mean[NS_];
#pragma unroll
        for (int n = 0; n < NS_; n++) {
            float s = 0.f;
            for (int t = tid; t < T_; t += 256) s += X[n][t];
            red[tid] = s; __syncthreads();
            for (int st = 128; st > 0; st >>= 1) {
                if (tid < st) red[tid] += red[tid + st];
                __syncthreads();
            }
            mean[n] = red[0] / (float)T_;
            __syncthreads();
        }

        float total = 0.f;
#pragma unroll
        for (int i = 0; i < NS_; i++)
#pragma unroll
            for (int j = 0; j <= i; j++) {
                float s = 0.f;
                for (int t = tid; t < T_; t += 256)
                    s += (X[i][t] - mean[i]) * (X[j][t] - mean[j]);
                red[tid] = s; __syncthreads();
                for (int st = 128; st > 0; st >>= 1) {
                    if (tid < st) red[tid] += red[tid + st];
                    __syncthreads();
                }
                if (tid == 0) {
                    const float c = red[0] / (float)(T_ - 1);
                    total += (i == j ? 1.0f : 2.0f) * fabsf(c);
                }
                __syncthreads();
            }
        if (tid == 0) g_bloss[b] = 0.5f * total;
    }
}

// --------------------------------- AV GEMM ---------------------------------
// grid (2, 4, 256): x=n0, y=n (A-tile sharers launch-adjacent), z=b*16+i,
// myi = 15-i (heavy tiles first).
__global__ void __launch_bounds__(256, 2) k_avgemm(float* __restrict__ out)
{
    extern __shared__ char sm[];
    const int tid = threadIdx.x, lane = tid & 31, wid = tid >> 5;
    const int n = blockIdx.y;
    const int b = blockIdx.z >> 4;
    const int myi = 15 - (int)(blockIdx.z & 15);
    const int m0 = myi * 128, n0 = blockIdx.x * 128;
    const int NC = myi * 2 + 2;            // causal: attn==0 beyond m0+128

    float acc[2][8][4] = {};
    gemm_core(sm, g_a16 + ((size_t)b * T_ + m0) * T_, T_,
                  g_vt16 + (((size_t)n * B_ + b) * R_ + n0) * T_, T_, NC, acc);

    float* C = out + ((size_t)b * NS_ + n) * T_ * R_;
    const int g = lane >> 2, tg = lane & 3;
    const int mOff = (wid & 3) * 32, nOff = (wid >> 2) * 64;
#pragma unroll
    for (int mt = 0; mt < 2; mt++)
#pragma unroll
        for (int nt = 0; nt < 8; nt++) {
            const int gc = n0 + nOff + nt * 8 + 2 * tg;
#pragma unroll
            for (int h = 0; h < 2; h++) {
                const int gr = m0 + mOff + mt * 16 + g + h * 8;
                *reinterpret_cast<float2*>(C + (size_t)gr * R_ + gc) =
                    make_float2(acc[mt][nt][h * 2 + 0], acc[mt][nt][h * 2 + 1]);
            }
        }
}

__global__ void k_final(float* __restrict__ out, long idx)
{
    float s = 0.f;
#pragma unroll
    for (int b = 0; b < B_; b++) s += g_bloss[b];
    out[idx] = s / (float)B_;
}

// ---------------------------------------------------------------------------
extern "C" void kernel_launch(void* const* d_in, const int* in_sizes, int n_in,
                              void* d_out, int out_size)
{
    (void)in_sizes; (void)n_in;
    const float* q  = (const float*)d_in[0];
    const float* k  = (const float*)d_in[1];
    const float* v  = (const float*)d_in[2];
    const float* wq = (const float*)d_in[3];
    const float* bq = (const float*)d_in[4];
    const float* wk = (const float*)d_in[5];
    const float* bk = (const float*)d_in[6];
    const float* wv = (const float*)d_in[7];
    const float* bv = (const float*)d_in[8];
    const float* wp = (const float*)d_in[9];
    float* out = (float*)d_out;

    static bool attr_set = false;
    if (!attr_set) {
        cudaFuncSetAttribute(k_mid,    cudaFuncAttributeMaxDynamicSharedMemorySize, SMEM_G);
        cudaFuncSetAttribute(k_avgemm, cudaFuncAttributeMaxDynamicSharedMemorySize, SMEM_G);
        attr_set = true;
    }

    const dim3 blk(256);
    k_cvt3<<<dim3(1024, 3), blk>>>(q, k, v);
    k_cvtw<<<dim3(64, 3),  blk>>>(wq, wk, wv);

    k_mid<<<PG_CTAS + VP_CTAS + SC_CTAS, blk, SMEM_G>>>(bq, bk, bv, wp);

    k_phase3<<<SM_BLOCKS + B_, blk>>>();

    k_avgemm<<<dim3(2, NS_, 256), blk, SMEM_G>>>(out);

    k_final<<<1, 1>>>(out, (long)out_size - 1);
}